// round 2
// baseline (speedup 1.0000x reference)
#include <cuda_runtime.h>

// ---------------------------------------------------------------------------
// Allegro GNN layer, fp32 with packed f32x2 FMA (FFMA2), sm_103a.
//   k_zero : zero env accumulators + output
//   k1     : geometry + bessel + MLP(40->64->128->128) + Wenv0, env scatter
//   k2a    : channel products, s_mix, v_mix (packed), scal0
//   k2b    : lat-update MLP (192->128->128) + residual
//   k2c    : Wenv1 (128->64) + env1 scatter
//   k3     : q0/q1 + final MLP (192->128->128) + residual, node scatter
// Activations stored DUPLICATED in shared ((v,v) pairs) so fma.rn.f32x2 gets
// its broadcast operand with a single LDS.64/LDS.128. Scatters use
// red.global.add.v4.f32.
// ---------------------------------------------------------------------------

#define NN 10000
#define NE 320000
typedef unsigned long long ULL;

__device__ float g_lat  [NE * 128];
__device__ float g_wedge[NE * 64];
__device__ float g_scal0[NE * 64];
__device__ float g_smix [NE * 32];
__device__ float g_vmix [NE * 128];   // padded: [e][m][4] = {v0,v1,v2,0}
__device__ float g_Y    [NE * 4];
__device__ float g_fcut [NE];
__device__ float g_env  [NN * 128];
__device__ float g_env1 [NN * 128];

#define F_RS40      0.15811388300841897f
#define F_RS64      0.125f
#define F_RS96      0.10206207261596575f
#define F_RS128     0.08838834764831845f
#define F_RS192     0.07216878364870323f
#define F_ISN       0.17677669529663689f
#define F_SQRT3     1.7320508075688772f
#define F_INV_SQRT3 0.5773502691896258f
#define F_INV_SQRT2 0.7071067811865476f
#define F_C_OLD     0.8944271909999159f
#define F_C_NEW     0.4472135954999579f
#define F_BESSEL    0.6324555320336759f
#define F_PI        3.14159265358979323846f
#define F_INV_RMAX  0.2f

__device__ __forceinline__ ULL fma2(ULL a, ULL b, ULL c) {
    ULL d;
    asm("fma.rn.f32x2 %0, %1, %2, %3;" : "=l"(d) : "l"(a), "l"(b), "l"(c));
    return d;
}

__device__ __forceinline__ void red4(float* p, float a, float b, float c, float d) {
    asm volatile("red.global.add.v4.f32 [%0], {%1,%2,%3,%4};"
                 :: "l"(p), "f"(a), "f"(b), "f"(c), "f"(d) : "memory");
}

__device__ __forceinline__ float silu_f(float v) {
    return v * __frcp_rn(1.0f + __expf(-v));
}

// ---------------------------------------------------------------------------
// Packed warp matvec: y = act(scale * (x @ W)).  x duplicated in shared
// (value o at xd[2o], xd[2o+1]).  W plain row-major [IN][OUT] in shared.
// Lane owns outputs OPL*lane..OPL*lane+OPL-1.  DUPOUT: write y duplicated.
// ---------------------------------------------------------------------------
template <int IN, int OUT, int EPW, bool SILU, bool DUPOUT>
__device__ __forceinline__ void pmatvec(
    const float* __restrict__ Wsh,
    const float* __restrict__ xd, int XS,
    float*       __restrict__ yd, int YS,
    const float* sc, int lane)
{
    constexpr int OPL = OUT / 32;
    constexpr int NP  = OPL / 2;
    ULL acc[EPW][NP];
#pragma unroll
    for (int e = 0; e < EPW; e++)
#pragma unroll
        for (int k = 0; k < NP; k++) acc[e][k] = 0ULL;

#pragma unroll 4
    for (int i = 0; i < IN; i += 2) {
        ULL w0[NP], w1[NP];
        if constexpr (OPL == 4) {
            ulonglong2 a = *reinterpret_cast<const ulonglong2*>(Wsh + i * OUT + 4 * lane);
            ulonglong2 b = *reinterpret_cast<const ulonglong2*>(Wsh + (i + 1) * OUT + 4 * lane);
            w0[0] = a.x; w0[1] = a.y; w1[0] = b.x; w1[1] = b.y;
        } else {
            w0[0] = *reinterpret_cast<const ULL*>(Wsh + i * OUT + 2 * lane);
            w1[0] = *reinterpret_cast<const ULL*>(Wsh + (i + 1) * OUT + 2 * lane);
        }
#pragma unroll
        for (int e = 0; e < EPW; e++) {
            ulonglong2 xp = *reinterpret_cast<const ulonglong2*>(xd + e * XS + 2 * i);
#pragma unroll
            for (int k = 0; k < NP; k++) {
                acc[e][k] = fma2(xp.x, w0[k], acc[e][k]);
                acc[e][k] = fma2(xp.y, w1[k], acc[e][k]);
            }
        }
    }

#pragma unroll
    for (int e = 0; e < EPW; e++) {
        float v[OPL];
#pragma unroll
        for (int k = 0; k < NP; k++) {
            union { ULL u; float2 f; } cv; cv.u = acc[e][k];
            v[2 * k]     = cv.f.x * sc[e];
            v[2 * k + 1] = cv.f.y * sc[e];
        }
        if (SILU) {
#pragma unroll
            for (int k = 0; k < OPL; k++) v[k] = silu_f(v[k]);
        }
        if (DUPOUT) {
            if constexpr (OPL == 4) {
#pragma unroll
                for (int k = 0; k < NP; k++) {
                    float4 t = make_float4(v[2 * k], v[2 * k], v[2 * k + 1], v[2 * k + 1]);
                    *reinterpret_cast<float4*>(yd + e * YS + 8 * lane + 4 * k) = t;
                }
            } else {
                float4 t = make_float4(v[0], v[0], v[1], v[1]);
                *reinterpret_cast<float4*>(yd + e * YS + 4 * lane) = t;
            }
        } else {
            if constexpr (OPL == 4) {
                *reinterpret_cast<float4*>(yd + e * YS + 4 * lane) =
                    make_float4(v[0], v[1], v[2], v[3]);
            } else {
                *reinterpret_cast<float2*>(yd + e * YS + 2 * lane) =
                    make_float2(v[0], v[1]);
            }
        }
    }
    __syncwarp();
}

// ---------------------------------------------------------------------------
__global__ void k_zero(float* __restrict__ out)
{
    int i = blockIdx.x * blockDim.x + threadIdx.x;
    int stride = gridDim.x * blockDim.x;
    for (; i < NN * 128; i += stride) {
        g_env[i]  = 0.0f;
        g_env1[i] = 0.0f;
        out[i]    = 0.0f;
    }
}

// ---------------------------------------------------------------------------
// K1: geometry + 2-body MLP + Wenv0 + env scatter.  EPW=3, buf 512/edge.
// ---------------------------------------------------------------------------
#define EPW1 3
__global__ void __launch_bounds__(256, 1) k1(
    const float* __restrict__ coords, const float* __restrict__ attrs,
    const int*   __restrict__ eidx,
    const float* __restrict__ W2b0, const float* __restrict__ W2b1,
    const float* __restrict__ W2b2, const float* __restrict__ Wenv0)
{
    extern __shared__ float sh[];
    float* sW0  = sh;                   // 40*64   = 2560
    float* sW1  = sW0 + 2560;           // 64*128  = 8192
    float* sW2  = sW1 + 8192;           // 128*128 = 16384
    float* sWe  = sW2 + 16384;          // 128*128 = 16384
    float* sbuf = sWe + 16384;          // 3*512 per warp

    int tid = threadIdx.x;
    for (int i = tid; i < 2560;  i += 256) sW0[i] = W2b0[i];
    for (int i = tid; i < 8192;  i += 256) sW1[i] = W2b1[i];
    for (int i = tid; i < 16384; i += 256) { sW2[i] = W2b2[i]; sWe[i] = Wenv0[i]; }
    __syncthreads();

    int warp = tid >> 5, lane = tid & 31;
    float* wb = sbuf + warp * (EPW1 * 512);
    int nwarp = gridDim.x * 8;
    int gw = blockIdx.x * 8 + warp;

    float sA[EPW1], sB[EPW1], sC[EPW1], sD[EPW1];
#pragma unroll
    for (int j = 0; j < EPW1; j++) { sA[j] = F_RS40; sB[j] = F_RS64; sD[j] = F_RS128; }

    for (int base = gw * EPW1; base < NE; base += nwarp * EPW1) {
        int   ctr[EPW1];
        float fc[EPW1], Y1[EPW1], Y2[EPW1], Y3[EPW1];
#pragma unroll
        for (int j = 0; j < EPW1; j++) {
            int e = base + j; if (e >= NE) e = NE - 1;
            int snd = eidx[e];
            int c   = eidx[NE + e];
            ctr[j] = c;
            float dx = coords[c * 3 + 0] - coords[snd * 3 + 0];
            float dy = coords[c * 3 + 1] - coords[snd * 3 + 1];
            float dz = coords[c * 3 + 2] - coords[snd * 3 + 2];
            float r2 = dx * dx + dy * dy + dz * dz + 1e-12f;
            float r  = sqrtf(r2);
            float inv_r = 1.0f / r;
            float u  = r * F_INV_RMAX;
            float u2 = u * u, u3 = u2 * u, u6 = u3 * u3, u7 = u6 * u, u8 = u7 * u;
            float f  = 1.0f - 28.0f * u6 + 48.0f * u7 - 21.0f * u8;
            if (u >= 1.0f) f = 0.0f;
            fc[j] = f;
            Y1[j] = F_SQRT3 * dx * inv_r;
            Y2[j] = F_SQRT3 * dy * inv_r;
            Y3[j] = F_SQRT3 * dz * inv_r;
            float* A = wb + j * 512;
            float av;
            if (lane < 16) av = attrs[c * 16 + lane];
            else           av = attrs[snd * 16 + (lane - 16)];
            *reinterpret_cast<float2*>(A + 2 * lane) = make_float2(av, av);
            if (lane < 8) {
                float b = F_BESSEL * __sinf((lane + 1) * F_PI * u) * inv_r * f;
                *reinterpret_cast<float2*>(A + 64 + 2 * lane) = make_float2(b, b);
            }
            sC[j] = F_RS128 * f;
        }
        __syncwarp();

        pmatvec<40, 64,  EPW1, true,  true>(sW0, wb,       512, wb + 256, 512, sA, lane);
        pmatvec<64, 128, EPW1, true,  true>(sW1, wb + 256, 512, wb,       512, sB, lane);
        pmatvec<128,128, EPW1, false, true>(sW2, wb,       512, wb + 256, 512, sC, lane); // lat dup
        // store lat
#pragma unroll
        for (int j = 0; j < EPW1; j++) {
            int e = base + j;
            if (e >= NE) break;
            float* B = wb + j * 512 + 256;
            float4 a = *reinterpret_cast<float4*>(B + 8 * lane);
            float4 b = *reinterpret_cast<float4*>(B + 8 * lane + 4);
            *reinterpret_cast<float4*>(&g_lat[(long)e * 128 + 4 * lane]) =
                make_float4(a.x, a.z, b.x, b.z);
        }
        pmatvec<128,128, EPW1, false, true>(sWe, wb + 256, 512, wb, 512, sD, lane); // w_all dup

#pragma unroll
        for (int j = 0; j < EPW1; j++) {
            int e = base + j;
            if (e >= NE) break;
            float* A = wb + j * 512;
            float we0 = A[4 * lane];
            float we1 = A[4 * lane + 2];
            *reinterpret_cast<float2*>(&g_wedge[e * 64 + 2 * lane]) = make_float2(we0, we1);
            float wv0 = A[128 + 4 * lane];
            float wv1 = A[128 + 4 * lane + 2];
            red4(&g_env[(long)ctr[j] * 128 + 4 * lane],
                 wv0, wv1 * Y1[j], wv1 * Y2[j], wv1 * Y3[j]);
            if (lane == 0) {
                g_fcut[e] = fc[j];
                *reinterpret_cast<float4*>(&g_Y[e * 4]) =
                    make_float4(1.0f, Y1[j], Y2[j], Y3[j]);
            }
        }
        __syncwarp();
    }
}

// ---------------------------------------------------------------------------
// K2a: equivariant products + s_mix + v_mix (packed) + scal0.
// ---------------------------------------------------------------------------
__global__ void __launch_bounds__(256) k2a(
    const int* __restrict__ eidx,
    const float* __restrict__ Ws0, const float* __restrict__ Wv0)
{
    __shared__ __align__(16) float sWs [64 * 32];
    __shared__ __align__(16) float sWvD[96 * 32 * 2];   // duplicated pairs
    __shared__ __align__(16) float stage[8][64];
    __shared__ __align__(16) float Pst[8][96 * 4];

    int tid = threadIdx.x;
    for (int i = tid; i < 64 * 32; i += 256) sWs[i] = Ws0[i];
    for (int i = tid; i < 96 * 32; i += 256) {
        float w = Wv0[i];
        sWvD[2 * i] = w; sWvD[2 * i + 1] = w;
    }
    __syncthreads();

    int warp = tid >> 5, lane = tid & 31;
    int gw = blockIdx.x * 8 + warp;
    int nw = gridDim.x * 8;

    for (int e = gw; e < NE; e += nw) {
        int c = eidx[NE + e];
        float2 we = *reinterpret_cast<const float2*>(&g_wedge[e * 64 + 2 * lane]);
        float4 en = *reinterpret_cast<const float4*>(&g_env[(long)c * 128 + 4 * lane]);
        float4 Yv = *reinterpret_cast<const float4*>(&g_Y[e * 4]);
        float fs  = we.x;
        float fv0 = we.y * Yv.y, fv1 = we.y * Yv.z, fv2 = we.y * Yv.w;
        float es  = en.x * F_ISN;
        float ev0 = en.y * F_ISN, ev1 = en.z * F_ISN, ev2 = en.w * F_ISN;

        float p0 = fs * es;
        float p1 = (fv0 * ev0 + fv1 * ev1 + fv2 * ev2) * F_INV_SQRT3;
        stage[warp][lane]      = p0;
        stage[warp][32 + lane] = p1;
        float* P = Pst[warp];
        *reinterpret_cast<float4*>(P + lane * 4) =
            make_float4(fs * ev0, fs * ev1, fs * ev2, 0.0f);
        *reinterpret_cast<float4*>(P + (32 + lane) * 4) =
            make_float4(fv0 * es, fv1 * es, fv2 * es, 0.0f);
        *reinterpret_cast<float4*>(P + (64 + lane) * 4) =
            make_float4((fv1 * ev2 - fv2 * ev1) * F_INV_SQRT2,
                        (fv2 * ev0 - fv0 * ev2) * F_INV_SQRT2,
                        (fv0 * ev1 - fv1 * ev0) * F_INV_SQRT2, 0.0f);
        __syncwarp();

        float sm = 0.0f;
#pragma unroll 4
        for (int i = 0; i < 64; i++) sm = fmaf(stage[warp][i], sWs[i * 32 + lane], sm);
        sm *= F_RS64;

        ULL a01 = 0ULL, a2x = 0ULL;
#pragma unroll 4
        for (int i = 0; i < 96; i++) {
            ULL wd = *reinterpret_cast<const ULL*>(sWvD + (i * 32 + lane) * 2);
            ulonglong2 pp = *reinterpret_cast<const ulonglong2*>(P + i * 4);
            a01 = fma2(pp.x, wd, a01);
            a2x = fma2(pp.y, wd, a2x);
        }
        union { ULL u; float2 f; } c01, c2x;
        c01.u = a01; c2x.u = a2x;
        float v0 = c01.f.x * F_RS96, v1 = c01.f.y * F_RS96, v2 = c2x.f.x * F_RS96;

        g_scal0[e * 64 + lane]      = p0;
        g_scal0[e * 64 + 32 + lane] = p1;
        g_smix[e * 32 + lane] = sm;
        *reinterpret_cast<float4*>(&g_vmix[(long)e * 128 + 4 * lane]) =
            make_float4(v0, v1, v2, 0.0f);
        __syncwarp();
    }
}

// ---------------------------------------------------------------------------
// K2b: lat update MLP (192->128->128) + residual.  EPW=3, buf 640/edge.
// X: lat dup [0..255], scal0 dup [256..383] (later overwritten by NL plain),
// H dup [384..639].
// ---------------------------------------------------------------------------
#define EPW2 3
__global__ void __launch_bounds__(256, 1) k2b(
    const int*   __restrict__ eidx,
    const float* __restrict__ Wlat0, const float* __restrict__ Wlat1)
{
    extern __shared__ float sh[];
    float* sL0  = sh;             // 192*128 = 24576
    float* sL1  = sL0 + 24576;    // 128*128 = 16384
    float* sbuf = sL1 + 16384;

    int tid = threadIdx.x;
    for (int i = tid; i < 24576; i += 256) sL0[i] = Wlat0[i];
    for (int i = tid; i < 16384; i += 256) sL1[i] = Wlat1[i];
    __syncthreads();

    int warp = tid >> 5, lane = tid & 31;
    float* wb = sbuf + warp * (EPW2 * 640);
    int nw = gridDim.x * 8;
    int gw = blockIdx.x * 8 + warp;

    float s0[EPW2], s1[EPW2];
#pragma unroll
    for (int j = 0; j < EPW2; j++) s0[j] = F_RS192;

    for (int base = gw * EPW2; base < NE; base += nw * EPW2) {
#pragma unroll
        for (int j = 0; j < EPW2; j++) {
            int e = base + j; if (e >= NE) e = NE - 1;
            float f = g_fcut[e];
            float* X = wb + j * 640;
            float4 lv = *reinterpret_cast<const float4*>(&g_lat[(long)e * 128 + 4 * lane]);
            *reinterpret_cast<float4*>(X + 8 * lane)     = make_float4(lv.x, lv.x, lv.y, lv.y);
            *reinterpret_cast<float4*>(X + 8 * lane + 4) = make_float4(lv.z, lv.z, lv.w, lv.w);
            float sa = g_scal0[e * 64 + lane];
            float sb = g_scal0[e * 64 + 32 + lane];
            *reinterpret_cast<float2*>(X + 256 + 2 * lane) = make_float2(sa, sa);
            *reinterpret_cast<float2*>(X + 320 + 2 * lane) = make_float2(sb, sb);
            s1[j] = F_RS128 * f;
        }
        __syncwarp();

        pmatvec<192, 128, EPW2, true,  true >(sL0, wb,       640, wb + 384, 640, s0, lane);
        pmatvec<128, 128, EPW2, false, false>(sL1, wb + 384, 640, wb + 256, 640, s1, lane);

#pragma unroll
        for (int j = 0; j < EPW2; j++) {
            int e = base + j;
            if (e >= NE) break;
            float* X = wb + j * 640;
            float4 a  = *reinterpret_cast<float4*>(X + 8 * lane);
            float4 b  = *reinterpret_cast<float4*>(X + 8 * lane + 4);
            float4 nl = *reinterpret_cast<float4*>(X + 256 + 4 * lane);
            float4 o;
            o.x = F_C_OLD * a.x + F_C_NEW * nl.x;
            o.y = F_C_OLD * a.z + F_C_NEW * nl.y;
            o.z = F_C_OLD * b.x + F_C_NEW * nl.z;
            o.w = F_C_OLD * b.z + F_C_NEW * nl.w;
            *reinterpret_cast<float4*>(&g_lat[(long)e * 128 + 4 * lane]) = o;
        }
        __syncwarp();
    }
}

// ---------------------------------------------------------------------------
// K2c: w_env1 = lat @ Wenv1 (128->64), env1 scatter.  EPW=4, buf 384/edge.
// ---------------------------------------------------------------------------
#define EPWC 4
__global__ void __launch_bounds__(256) k2c(
    const int* __restrict__ eidx, const float* __restrict__ Wenv1)
{
    extern __shared__ float sh[];
    float* sE1  = sh;             // 128*64 = 8192
    float* sbuf = sE1 + 8192;

    int tid = threadIdx.x;
    for (int i = tid; i < 8192; i += 256) sE1[i] = Wenv1[i];
    __syncthreads();

    int warp = tid >> 5, lane = tid & 31;
    float* wb = sbuf + warp * (EPWC * 384);
    int nw = gridDim.x * 8;
    int gw = blockIdx.x * 8 + warp;

    float sc[EPWC];
#pragma unroll
    for (int j = 0; j < EPWC; j++) sc[j] = F_RS128;

    for (int base = gw * EPWC; base < NE; base += nw * EPWC) {
#pragma unroll
        for (int j = 0; j < EPWC; j++) {
            int e = base + j; if (e >= NE) e = NE - 1;
            float* X = wb + j * 384;
            float4 lv = *reinterpret_cast<const float4*>(&g_lat[(long)e * 128 + 4 * lane]);
            *reinterpret_cast<float4*>(X + 8 * lane)     = make_float4(lv.x, lv.x, lv.y, lv.y);
            *reinterpret_cast<float4*>(X + 8 * lane + 4) = make_float4(lv.z, lv.z, lv.w, lv.w);
        }
        __syncwarp();

        pmatvec<128, 64, EPWC, false, true>(sE1, wb, 384, wb + 256, 384, sc, lane);

#pragma unroll
        for (int j = 0; j < EPWC; j++) {
            int e = base + j;
            if (e >= NE) break;
            int c = eidx[NE + e];
            float* Yp = &g_Y[e * 4];
            float Y1 = Yp[1], Y2 = Yp[2], Y3 = Yp[3];
            float* X = wb + j * 384;
            float w0 = X[256 + 4 * lane];
            float w1 = X[256 + 4 * lane + 2];
            red4(&g_env1[(long)c * 128 + 4 * lane],
                 w0, w1 * Y1, w1 * Y2, w1 * Y3);
        }
        __syncwarp();
    }
}

// ---------------------------------------------------------------------------
// K3: q0/q1 + final MLP (192->128->128) + residual + node scatter.  EPW=3.
// ---------------------------------------------------------------------------
#define EPW3 3
__global__ void __launch_bounds__(256, 1) k3(
    const int*   __restrict__ eidx,
    const float* __restrict__ Wfin0, const float* __restrict__ Wfin1,
    float* __restrict__ out)
{
    extern __shared__ float sh[];
    float* sF0  = sh;             // 192*128 = 24576
    float* sF1  = sF0 + 24576;    // 128*128 = 16384
    float* sbuf = sF1 + 16384;

    int tid = threadIdx.x;
    for (int i = tid; i < 24576; i += 256) sF0[i] = Wfin0[i];
    for (int i = tid; i < 16384; i += 256) sF1[i] = Wfin1[i];
    __syncthreads();

    int warp = tid >> 5, lane = tid & 31;
    float* wb = sbuf + warp * (EPW3 * 640);
    int nw = gridDim.x * 8;
    int gw = blockIdx.x * 8 + warp;

    float s0[EPW3], s1[EPW3];
    int ctr[EPW3];
#pragma unroll
    for (int j = 0; j < EPW3; j++) s0[j] = F_RS192;

    for (int base = gw * EPW3; base < NE; base += nw * EPW3) {
#pragma unroll
        for (int j = 0; j < EPW3; j++) {
            int e = base + j; if (e >= NE) e = NE - 1;
            int c = eidx[NE + e];
            ctr[j] = c;
            float f = g_fcut[e];
            float* X = wb + j * 640;
            float4 lv = *reinterpret_cast<const float4*>(&g_lat[(long)e * 128 + 4 * lane]);
            *reinterpret_cast<float4*>(X + 8 * lane)     = make_float4(lv.x, lv.x, lv.y, lv.y);
            *reinterpret_cast<float4*>(X + 8 * lane + 4) = make_float4(lv.z, lv.z, lv.w, lv.w);
            float4 e1 = *reinterpret_cast<const float4*>(&g_env1[(long)c * 128 + 4 * lane]);
            float es  = e1.x * F_ISN;
            float ev0 = e1.y * F_ISN, ev1 = e1.z * F_ISN, ev2 = e1.w * F_ISN;
            float sm  = g_smix[e * 32 + lane];
            float4 vm = *reinterpret_cast<const float4*>(&g_vmix[(long)e * 128 + 4 * lane]);
            float q0  = sm * es;
            float q1  = (vm.x * ev0 + vm.y * ev1 + vm.z * ev2) * F_INV_SQRT3;
            *reinterpret_cast<float2*>(X + 256 + 2 * lane) = make_float2(q0, q0);
            *reinterpret_cast<float2*>(X + 320 + 2 * lane) = make_float2(q1, q1);
            s1[j] = F_RS128 * f;
        }
        __syncwarp();

        pmatvec<192, 128, EPW3, true,  true >(sF0, wb,       640, wb + 384, 640, s0, lane);
        pmatvec<128, 128, EPW3, false, false>(sF1, wb + 384, 640, wb + 256, 640, s1, lane);

#pragma unroll
        for (int j = 0; j < EPW3; j++) {
            int e = base + j;
            if (e >= NE) break;
            float* X = wb + j * 640;
            float4 a  = *reinterpret_cast<float4*>(X + 8 * lane);
            float4 b  = *reinterpret_cast<float4*>(X + 8 * lane + 4);
            float4 nl = *reinterpret_cast<float4*>(X + 256 + 4 * lane);
            float o0 = (F_C_OLD * a.x + F_C_NEW * nl.x) * F_ISN;
            float o1 = (F_C_OLD * a.z + F_C_NEW * nl.y) * F_ISN;
            float o2 = (F_C_OLD * b.x + F_C_NEW * nl.z) * F_ISN;
            float o3 = (F_C_OLD * b.z + F_C_NEW * nl.w) * F_ISN;
            red4(&out[(long)ctr[j] * 128 + 4 * lane], o0, o1, o2, o3);
        }
        __syncwarp();
    }
}

// ---------------------------------------------------------------------------
extern "C" void kernel_launch(void* const* d_in, const int* in_sizes, int n_in,
                              void* d_out, int out_size)
{
    const float* coords = (const float*)d_in[0];
    const float* attrs  = (const float*)d_in[1];
    const int*   eidx   = (const int*)  d_in[2];
    const float* W2b0   = (const float*)d_in[3];
    const float* W2b1   = (const float*)d_in[4];
    const float* W2b2   = (const float*)d_in[5];
    const float* Wenv0  = (const float*)d_in[6];
    const float* Wlat0  = (const float*)d_in[7];
    const float* Wlat1  = (const float*)d_in[8];
    const float* Ws0    = (const float*)d_in[9];
    const float* Wv0    = (const float*)d_in[10];
    const float* Wenv1  = (const float*)d_in[11];
    const float* Wfin0  = (const float*)d_in[12];
    const float* Wfin1  = (const float*)d_in[13];
    float* out = (float*)d_out;

    const size_t smem1  = (size_t)(43520 + EPW1 * 512 * 8) * sizeof(float); // 223232
    const size_t smem2b = (size_t)(40960 + EPW2 * 640 * 8) * sizeof(float); // 225280
    const size_t smem2c = (size_t)(8192  + EPWC * 384 * 8) * sizeof(float); // 81920
    const size_t smem3  = (size_t)(40960 + EPW3 * 640 * 8) * sizeof(float); // 225280

    cudaFuncSetAttribute(k1,  cudaFuncAttributeMaxDynamicSharedMemorySize, (int)smem1);
    cudaFuncSetAttribute(k2b, cudaFuncAttributeMaxDynamicSharedMemorySize, (int)smem2b);
    cudaFuncSetAttribute(k2c, cudaFuncAttributeMaxDynamicSharedMemorySize, (int)smem2c);
    cudaFuncSetAttribute(k3,  cudaFuncAttributeMaxDynamicSharedMemorySize, (int)smem3);

    k_zero<<<512, 256>>>(out);
    k1 <<<148, 256, smem1 >>>(coords, attrs, eidx, W2b0, W2b1, W2b2, Wenv0);
    k2a<<<592, 256>>>(eidx, Ws0, Wv0);
    k2b<<<148, 256, smem2b>>>(eidx, Wlat0, Wlat1);
    k2c<<<296, 256, smem2c>>>(eidx, Wenv1);
    k3 <<<148, 256, smem3 >>>(eidx, Wfin0, Wfin1, out);
}